// round 4
// baseline (speedup 1.0000x reference)
#include <cuda_runtime.h>
#include <cstdint>

#define B_ROWS 16384
#define C_DIM  1024
#define N_ITERS 16

// ---- GEMM config: 128x128 tile, BK=32, 3-stage cp.async, 256 threads ----
#define TILE_M 128
#define TILE_N 128
#define BKC    32                       // 32 floats = 128B row (SW128 atom)
#define NSTAGE 3
#define A_STAGE_BYTES (TILE_M * 128)    // 16KB
#define B_STAGE_BYTES (TILE_N * 128)    // 16KB
#define STAGE_BYTES   (A_STAGE_BYTES + B_STAGE_BYTES)
#define SMEM_TOTAL    (NSTAGE * STAGE_BYTES + 1024)
#define KCHUNKS       (C_DIM / BKC)     // 32
#define GEMM_THREADS  256

// ---------------- static scratch ----------------
__device__ float g_h1[(size_t)B_ROWS * C_DIM];
__device__ float g_d1[(size_t)B_ROWS * C_DIM];
__device__ float g_h2[(size_t)B_ROWS * C_DIM];
__device__ float g_d2[(size_t)B_ROWS * C_DIM];
__device__ float g_t1[(size_t)B_ROWS * C_DIM];
__device__ float g_t2[(size_t)B_ROWS * C_DIM];
__device__ float g_w [(size_t)B_ROWS * C_DIM];
__device__ float g_yr[(size_t)B_ROWS * C_DIM];
__device__ float g_vr[(size_t)B_ROWS * C_DIM];
__device__ float g_w1t[(size_t)C_DIM * C_DIM];
__device__ float g_w2t[(size_t)C_DIM * C_DIM];
__device__ float g_w3t[(size_t)C_DIM * C_DIM];
__device__ float g_w1r[(size_t)C_DIM * C_DIM];
__device__ float g_w2r[(size_t)C_DIM * C_DIM];
__device__ float g_w3r[(size_t)C_DIM * C_DIM];

// ---------------- helpers ----------------
__device__ __forceinline__ float to_tf32(float x) {
    unsigned r;
    asm("cvt.rna.tf32.f32 %0, %1;" : "=r"(r) : "f"(x));
    return __uint_as_float(r);
}

__device__ __forceinline__ uint32_t smem_u32(const void* p) {
    uint32_t a;
    asm("{ .reg .u64 t; cvta.to.shared.u64 t, %1; cvt.u32.u64 %0, t; }" : "=r"(a) : "l"(p));
    return a;
}

__device__ __forceinline__ unsigned lds_u32(uint32_t addr) {
    unsigned v;
    asm volatile("ld.shared.b32 %0, [%1];" : "=r"(v) : "r"(addr));
    return v;
}

#define MMA_TF32(C0, C1, C2, C3, A0, A1, A2, A3, Bb0, Bb1)                          \
    asm volatile(                                                                   \
        "mma.sync.aligned.m16n8k8.row.col.f32.tf32.tf32.f32 "                       \
        "{%0,%1,%2,%3}, {%4,%5,%6,%7}, {%8,%9}, {%0,%1,%2,%3};"                     \
        : "+f"(C0), "+f"(C1), "+f"(C2), "+f"(C3)                                    \
        : "r"(A0), "r"(A1), "r"(A2), "r"(A3), "r"(Bb0), "r"(Bb1))

constexpr int EPI_ELU  = 0;  // out0 = tf32(elu(c+bias)), out1 = elu'(c+bias)
constexpr int EPI_ADDY = 1;  // out0 = aux + c + bias  (full fp32)
constexpr int EPI_MULD = 2;  // out0 = tf32(c * aux)
constexpr int EPI_LAST = 3;  // out0 = tf32(c); acc[row] += alpha * sum(c*aux)

// NT GEMM: out[m,n] = sum_k A[m,k] * Bm[n,k];  inputs pre-rounded to tf32
template <int EPI>
__global__ void __launch_bounds__(GEMM_THREADS, 2)
gemm_nt(const float* __restrict__ A, const float* __restrict__ Bm,
        const float* __restrict__ bias,
        float* __restrict__ out0, float* __restrict__ out1,
        const float* __restrict__ aux,
        float alpha, float* __restrict__ acc)
{
    extern __shared__ __align__(16) char dsm[];
    const uint32_t sbase = (smem_u32(dsm) + 1023u) & ~1023u;

    const int tid  = threadIdx.x;
    const int lane = tid & 31;
    const int warp = tid >> 5;
    const int wm   = warp & 3;   // 4 warps along M (32 rows)
    const int wn   = warp >> 2;  // 2 warps along N (64 cols)
    const int g    = lane >> 2;
    const int t    = lane & 3;

    const int brow = blockIdx.y * TILE_M;
    const int bcol = blockIdx.x * TILE_N;
    const float* Abase = A  + (size_t)brow * C_DIM;
    const float* Bbase = Bm + (size_t)bcol * C_DIM;

    float c[2][8][4];
#pragma unroll
    for (int i = 0; i < 2; ++i)
#pragma unroll
        for (int j = 0; j < 8; ++j)
#pragma unroll
            for (int r = 0; r < 4; ++r) c[i][j][r] = 0.f;

// stage fill: 128 rows x 128B per operand; 256 threads x 4 x 16B each
#define LOADCH(ch, st)                                                            \
    do {                                                                          \
        const uint32_t sa_ = sbase + (st) * STAGE_BYTES;                          \
        const uint32_t sb_ = sa_ + A_STAGE_BYTES;                                 \
        const float* ag_ = Abase + (ch) * BKC;                                    \
        const float* bg_ = Bbase + (ch) * BKC;                                    \
        _Pragma("unroll")                                                         \
        for (int i_ = 0; i_ < 4; ++i_) {                                          \
            int l_ = i_ * GEMM_THREADS + tid; int r_ = l_ >> 3; int q_ = l_ & 7;  \
            uint32_t d_ = sa_ + (uint32_t)(r_ * 128) + (uint32_t)((q_ ^ (r_ & 7)) << 4); \
            const float* s_ = ag_ + (size_t)r_ * C_DIM + q_ * 4;                  \
            asm volatile("cp.async.cg.shared.global [%0], [%1], 16;"              \
                         :: "r"(d_), "l"(s_) : "memory");                         \
        }                                                                         \
        _Pragma("unroll")                                                         \
        for (int i_ = 0; i_ < 4; ++i_) {                                          \
            int l_ = i_ * GEMM_THREADS + tid; int r_ = l_ >> 3; int q_ = l_ & 7;  \
            uint32_t d_ = sb_ + (uint32_t)(r_ * 128) + (uint32_t)((q_ ^ (r_ & 7)) << 4); \
            const float* s_ = bg_ + (size_t)r_ * C_DIM + q_ * 4;                  \
            asm volatile("cp.async.cg.shared.global [%0], [%1], 16;"              \
                         :: "r"(d_), "l"(s_) : "memory");                         \
        }                                                                         \
        asm volatile("cp.async.commit_group;" ::: "memory");                      \
    } while (0)

    LOADCH(0, 0);
    LOADCH(1, 1);

#pragma unroll 1
    for (int ch = 0; ch < KCHUNKS; ++ch) {
        const int s = ch % NSTAGE;
        asm volatile("cp.async.wait_group 1;" ::: "memory");
        __syncthreads();

        // issue next stage first so LDGSTS overlaps the MMA block
        if (ch + 2 < KCHUNKS) {
            const int s2 = (ch + 2) % NSTAGE;
            LOADCH(ch + 2, s2);
        } else {
            asm volatile("cp.async.commit_group;" ::: "memory");
        }

        const uint32_t sa = sbase + s * STAGE_BYTES;
        const uint32_t sb = sa + A_STAGE_BYTES;
        // per-thread bases; swizzle: element (row, k) lives at chunk (k/4)^(row&7),
        // and (row&7) == g for every row this thread touches
        const uint32_t abase = sa + (uint32_t)((wm * 32 + g) * 128 + t * 4);
        const uint32_t bbase = sb + (uint32_t)((wn * 64 + g) * 128 + t * 4);

#pragma unroll
        for (int ks = 0; ks < 4; ++ks) {
            const uint32_t x0 = (uint32_t)(((2 * ks)     ^ g) << 4);
            const uint32_t x1 = (uint32_t)(((2 * ks + 1) ^ g) << 4);

            unsigned af[2][4];
#pragma unroll
            for (int mt = 0; mt < 2; ++mt) {
                const uint32_t rb = abase + (uint32_t)(mt * 16 * 128);
                af[mt][0] = lds_u32(rb + x0);
                af[mt][1] = lds_u32(rb + 8 * 128 + x0);
                af[mt][2] = lds_u32(rb + x1);
                af[mt][3] = lds_u32(rb + 8 * 128 + x1);
            }
            unsigned bf[8][2];
#pragma unroll
            for (int nt = 0; nt < 8; ++nt) {
                const uint32_t rb = bbase + (uint32_t)(nt * 8 * 128);
                bf[nt][0] = lds_u32(rb + x0);
                bf[nt][1] = lds_u32(rb + x1);
            }
#pragma unroll
            for (int mt = 0; mt < 2; ++mt)
#pragma unroll
                for (int nt = 0; nt < 8; ++nt)
                    MMA_TF32(c[mt][nt][0], c[mt][nt][1], c[mt][nt][2], c[mt][nt][3],
                             af[mt][0], af[mt][1], af[mt][2], af[mt][3],
                             bf[nt][0], bf[nt][1]);
        }
    }
#undef LOADCH

    // ---------------- epilogue ----------------
    float rs[2][2];
    rs[0][0] = rs[0][1] = rs[1][0] = rs[1][1] = 0.f;

#pragma unroll
    for (int mt = 0; mt < 2; ++mt) {
        const int row0 = brow + wm * 32 + mt * 16 + g;
#pragma unroll
        for (int nt = 0; nt < 8; ++nt) {
            const int col = bcol + wn * 64 + nt * 8 + 2 * t;
#pragma unroll
            for (int h = 0; h < 2; ++h) {
                const int row = row0 + h * 8;
                const size_t idx = (size_t)row * C_DIM + col;
                float v0 = c[mt][nt][h * 2 + 0];
                float v1 = c[mt][nt][h * 2 + 1];
                if (EPI == EPI_ELU) {
                    float2 bb = *(const float2*)&bias[col];
                    float a0 = v0 + bb.x, a1 = v1 + bb.y;
                    float h0 = (a0 > 0.f) ? a0 : expm1f(a0);
                    float h1 = (a1 > 0.f) ? a1 : expm1f(a1);
                    float e0 = (a0 > 0.f) ? 1.f : h0 + 1.f;
                    float e1 = (a1 > 0.f) ? 1.f : h1 + 1.f;
                    *(float2*)&out0[idx] = make_float2(to_tf32(h0), to_tf32(h1));
                    *(float2*)&out1[idx] = make_float2(e0, e1);
                } else if (EPI == EPI_ADDY) {
                    float2 bb = *(const float2*)&bias[col];
                    float2 yv = *(const float2*)&aux[idx];
                    *(float2*)&out0[idx] = make_float2(v0 + bb.x + yv.x, v1 + bb.y + yv.y);
                } else if (EPI == EPI_MULD) {
                    float2 dv = *(const float2*)&aux[idx];
                    *(float2*)&out0[idx] = make_float2(to_tf32(v0 * dv.x), to_tf32(v1 * dv.y));
                } else {  // EPI_LAST
                    float2 vv = *(const float2*)&aux[idx];
                    rs[mt][h] += v0 * vv.x + v1 * vv.y;
                    *(float2*)&out0[idx] = make_float2(to_tf32(v0), to_tf32(v1));
                }
            }
        }
    }

    if (EPI == EPI_LAST) {
#pragma unroll
        for (int mt = 0; mt < 2; ++mt)
#pragma unroll
            for (int h = 0; h < 2; ++h) {
                float s = rs[mt][h];
                s += __shfl_xor_sync(0xffffffffu, s, 1);
                s += __shfl_xor_sync(0xffffffffu, s, 2);
                if (t == 0)
                    atomicAdd(&acc[brow + wm * 32 + mt * 16 + g + h * 8], alpha * s);
            }
    }
}

// ---------------- aux kernels ----------------
__global__ void transpose_round(const float* __restrict__ in, float* __restrict__ out)
{
    __shared__ float tile[32][33];
    int x = blockIdx.x * 32 + threadIdx.x;
    int y = blockIdx.y * 32 + threadIdx.y;
#pragma unroll
    for (int i = 0; i < 32; i += 8)
        tile[threadIdx.y + i][threadIdx.x] = in[(size_t)(y + i) * C_DIM + x];
    __syncthreads();
    x = blockIdx.y * 32 + threadIdx.x;
    y = blockIdx.x * 32 + threadIdx.y;
#pragma unroll
    for (int i = 0; i < 32; i += 8)
        out[(size_t)(y + i) * C_DIM + x] = to_tf32(tile[threadIdx.x][threadIdx.y + i]);
}

__global__ void round_copy(const float* __restrict__ in, float* __restrict__ out)
{
    int i = (blockIdx.x * 256 + threadIdx.x) * 4;
    float4 v = *(const float4*)(in + i);
    v.x = to_tf32(v.x); v.y = to_tf32(v.y); v.z = to_tf32(v.z); v.w = to_tf32(v.w);
    *(float4*)(out + i) = v;
}

__global__ void copy_f32(const float* __restrict__ in, float* __restrict__ out, int n)
{
    int i = blockIdx.x * blockDim.x + threadIdx.x;
    if (i < n) out[i] = in[i];
}

// ---------------- launch ----------------
extern "C" void kernel_launch(void* const* d_in, const int* in_sizes, int n_in,
                              void* d_out, int out_size)
{
    (void)in_sizes; (void)n_in; (void)out_size;

    const float* y   = (const float*)d_in[0];
    const float* ldj = (const float*)d_in[1];
    const float* v   = (const float*)d_in[2];
    const float* W1  = (const float*)d_in[3];
    const float* b1  = (const float*)d_in[4];
    const float* W2  = (const float*)d_in[5];
    const float* b2  = (const float*)d_in[6];
    const float* W3  = (const float*)d_in[7];
    const float* b3  = (const float*)d_in[8];

    float* zout  = (float*)d_out;
    float* ldout = zout + (size_t)B_ROWS * C_DIM;

    float *h1, *d1, *h2, *d2, *t1, *t2, *wb, *yr, *vr;
    float *w1t, *w2t, *w3t, *w1r, *w2r, *w3r;
    cudaGetSymbolAddress((void**)&h1,  g_h1);
    cudaGetSymbolAddress((void**)&d1,  g_d1);
    cudaGetSymbolAddress((void**)&h2,  g_h2);
    cudaGetSymbolAddress((void**)&d2,  g_d2);
    cudaGetSymbolAddress((void**)&t1,  g_t1);
    cudaGetSymbolAddress((void**)&t2,  g_t2);
    cudaGetSymbolAddress((void**)&wb,  g_w);
    cudaGetSymbolAddress((void**)&yr,  g_yr);
    cudaGetSymbolAddress((void**)&vr,  g_vr);
    cudaGetSymbolAddress((void**)&w1t, g_w1t);
    cudaGetSymbolAddress((void**)&w2t, g_w2t);
    cudaGetSymbolAddress((void**)&w3t, g_w3t);
    cudaGetSymbolAddress((void**)&w1r, g_w1r);
    cudaGetSymbolAddress((void**)&w2r, g_w2r);
    cudaGetSymbolAddress((void**)&w3r, g_w3r);

    cudaFuncSetAttribute(gemm_nt<EPI_ELU >, cudaFuncAttributeMaxDynamicSharedMemorySize, SMEM_TOTAL);
    cudaFuncSetAttribute(gemm_nt<EPI_ADDY>, cudaFuncAttributeMaxDynamicSharedMemorySize, SMEM_TOTAL);
    cudaFuncSetAttribute(gemm_nt<EPI_MULD>, cudaFuncAttributeMaxDynamicSharedMemorySize, SMEM_TOTAL);
    cudaFuncSetAttribute(gemm_nt<EPI_LAST>, cudaFuncAttributeMaxDynamicSharedMemorySize, SMEM_TOTAL);

    dim3 tgrid(C_DIM / 32, C_DIM / 32), tblk(32, 8);
    transpose_round<<<tgrid, tblk>>>(W1, w1t);
    transpose_round<<<tgrid, tblk>>>(W2, w2t);
    transpose_round<<<tgrid, tblk>>>(W3, w3t);

    const int wn = C_DIM * C_DIM / 1024;
    round_copy<<<wn, 256>>>(W1, w1r);
    round_copy<<<wn, 256>>>(W2, w2r);
    round_copy<<<wn, 256>>>(W3, w3r);
    const int bn = B_ROWS * C_DIM / 1024;
    round_copy<<<bn, 256>>>(y, yr);
    round_copy<<<bn, 256>>>(v, vr);

    copy_f32<<<B_ROWS / 256, 256>>>(ldj, ldout, B_ROWS);

    dim3 ggrid(C_DIM / TILE_N, B_ROWS / TILE_M);   // (8, 128)

    // forward
    gemm_nt<EPI_ELU ><<<ggrid, GEMM_THREADS, SMEM_TOTAL>>>(yr, w1r, b1, h1, d1, nullptr, 0.f, nullptr);
    gemm_nt<EPI_ELU ><<<ggrid, GEMM_THREADS, SMEM_TOTAL>>>(h1, w2r, b2, h2, d2, nullptr, 0.f, nullptr);
    gemm_nt<EPI_ADDY><<<ggrid, GEMM_THREADS, SMEM_TOTAL>>>(h2, w3r, b3, zout, nullptr, y, 0.f, nullptr);

    // power-series VJP iterations
    const float* wcur = vr;
    for (int k = 1; k <= N_ITERS; ++k) {
        gemm_nt<EPI_MULD><<<ggrid, GEMM_THREADS, SMEM_TOTAL>>>(wcur, w3t, nullptr, t1, nullptr, d2, 0.f, nullptr);
        gemm_nt<EPI_MULD><<<ggrid, GEMM_THREADS, SMEM_TOTAL>>>(t1,   w2t, nullptr, t2, nullptr, d1, 0.f, nullptr);
        const float alpha = ((k & 1) ? 1.f : -1.f) / (float)k;
        gemm_nt<EPI_LAST><<<ggrid, GEMM_THREADS, SMEM_TOTAL>>>(t2,   w1t, nullptr, wb, nullptr, v, alpha, ldout);
        wcur = wb;
    }
}

// round 5
// speedup vs baseline: 2.7549x; 2.7549x over previous
#include <cuda_runtime.h>
#include <cuda_fp16.h>
#include <cstdint>

#define B_ROWS 16384
#define C_DIM  1024
#define N_ITERS 16

// ---- GEMM config: 128x128 tile, BK=64 halves (128B rows), 3-stage cp.async ----
#define TILE_M 128
#define TILE_N 128
#define BKC    64                       // 64 halves = 128B row
#define NSTAGE 3
#define A_STAGE_BYTES (TILE_M * 128)    // 16KB
#define B_STAGE_BYTES (TILE_N * 128)    // 16KB
#define STAGE_BYTES   (A_STAGE_BYTES + B_STAGE_BYTES)
#define SMEM_TOTAL    (NSTAGE * STAGE_BYTES + 1024)
#define KCHUNKS       (C_DIM / BKC)     // 16
#define GEMM_THREADS  256

// ---------------- static scratch ----------------
__device__ __half g_h1[(size_t)B_ROWS * C_DIM];
__device__ __half g_h2[(size_t)B_ROWS * C_DIM];
__device__ __half g_t1[(size_t)B_ROWS * C_DIM];
__device__ __half g_t2[(size_t)B_ROWS * C_DIM];
__device__ __half g_w [(size_t)B_ROWS * C_DIM];
__device__ __half g_yh[(size_t)B_ROWS * C_DIM];
__device__ __half g_vh[(size_t)B_ROWS * C_DIM];
__device__ float  g_d1[(size_t)B_ROWS * C_DIM];
__device__ float  g_d2[(size_t)B_ROWS * C_DIM];
__device__ __half g_w1h [(size_t)C_DIM * C_DIM];
__device__ __half g_w2h [(size_t)C_DIM * C_DIM];
__device__ __half g_w3h [(size_t)C_DIM * C_DIM];
__device__ __half g_w1th[(size_t)C_DIM * C_DIM];
__device__ __half g_w2th[(size_t)C_DIM * C_DIM];
__device__ __half g_w3th[(size_t)C_DIM * C_DIM];

// ---------------- helpers ----------------
__device__ __forceinline__ uint32_t smem_u32(const void* p) {
    uint32_t a;
    asm("{ .reg .u64 t; cvta.to.shared.u64 t, %1; cvt.u32.u64 %0, t; }" : "=r"(a) : "l"(p));
    return a;
}

__device__ __forceinline__ unsigned lds_u32(uint32_t addr) {
    unsigned v;
    asm volatile("ld.shared.b32 %0, [%1];" : "=r"(v) : "r"(addr));
    return v;
}

#define MMA_F16(C0, C1, C2, C3, A0, A1, A2, A3, Bb0, Bb1)                           \
    asm volatile(                                                                   \
        "mma.sync.aligned.m16n8k16.row.col.f32.f16.f16.f32 "                        \
        "{%0,%1,%2,%3}, {%4,%5,%6,%7}, {%8,%9}, {%0,%1,%2,%3};"                     \
        : "+f"(C0), "+f"(C1), "+f"(C2), "+f"(C3)                                    \
        : "r"(A0), "r"(A1), "r"(A2), "r"(A3), "r"(Bb0), "r"(Bb1))

constexpr int EPI_ELU  = 0;  // out0(half) = elu(c+bias), out1(f32) = elu'(c+bias)
constexpr int EPI_ADDY = 1;  // out0(f32)  = aux + c + bias
constexpr int EPI_MULD = 2;  // out0(half) = c * aux
constexpr int EPI_LAST = 3;  // out0(half) = c; acc[row] += alpha * sum(c*aux)

// NT GEMM: out[m,n] = sum_k A[m,k] * Bm[n,k];  A,Bm are fp16, accum fp32
template <int EPI>
__global__ void __launch_bounds__(GEMM_THREADS, 2)
gemm_nt(const __half* __restrict__ A, const __half* __restrict__ Bm,
        const float* __restrict__ bias,
        void* __restrict__ out0, float* __restrict__ out1,
        const float* __restrict__ aux,
        float alpha, float* __restrict__ acc)
{
    extern __shared__ __align__(16) char dsm[];
    const uint32_t sbase = (smem_u32(dsm) + 1023u) & ~1023u;

    const int tid  = threadIdx.x;
    const int lane = tid & 31;
    const int warp = tid >> 5;
    const int wm   = warp & 3;   // 4 warps along M (32 rows)
    const int wn   = warp >> 2;  // 2 warps along N (64 cols)
    const int g    = lane >> 2;
    const int t    = lane & 3;

    const int brow = blockIdx.y * TILE_M;
    const int bcol = blockIdx.x * TILE_N;
    const __half* Abase = A  + (size_t)brow * C_DIM;
    const __half* Bbase = Bm + (size_t)bcol * C_DIM;

    float c[2][8][4];
#pragma unroll
    for (int i = 0; i < 2; ++i)
#pragma unroll
        for (int j = 0; j < 8; ++j)
#pragma unroll
            for (int r = 0; r < 4; ++r) c[i][j][r] = 0.f;

// stage fill: 128 rows x 128B per operand; 256 threads x 4 x 16B per operand
#define LOADCH(ch, st)                                                            \
    do {                                                                          \
        const uint32_t sa_ = sbase + (st) * STAGE_BYTES;                          \
        const uint32_t sb_ = sa_ + A_STAGE_BYTES;                                 \
        const __half* ag_ = Abase + (ch) * BKC;                                   \
        const __half* bg_ = Bbase + (ch) * BKC;                                   \
        _Pragma("unroll")                                                         \
        for (int i_ = 0; i_ < 4; ++i_) {                                          \
            int l_ = i_ * GEMM_THREADS + tid; int r_ = l_ >> 3; int q_ = l_ & 7;  \
            uint32_t d_ = sa_ + (uint32_t)(r_ * 128) + (uint32_t)((q_ ^ (r_ & 7)) << 4); \
            const __half* s_ = ag_ + (size_t)r_ * C_DIM + q_ * 8;                 \
            asm volatile("cp.async.cg.shared.global [%0], [%1], 16;"              \
                         :: "r"(d_), "l"(s_) : "memory");                         \
        }                                                                         \
        _Pragma("unroll")                                                         \
        for (int i_ = 0; i_ < 4; ++i_) {                                          \
            int l_ = i_ * GEMM_THREADS + tid; int r_ = l_ >> 3; int q_ = l_ & 7;  \
            uint32_t d_ = sb_ + (uint32_t)(r_ * 128) + (uint32_t)((q_ ^ (r_ & 7)) << 4); \
            const __half* s_ = bg_ + (size_t)r_ * C_DIM + q_ * 8;                 \
            asm volatile("cp.async.cg.shared.global [%0], [%1], 16;"              \
                         :: "r"(d_), "l"(s_) : "memory");                         \
        }                                                                         \
        asm volatile("cp.async.commit_group;" ::: "memory");                      \
    } while (0)

    LOADCH(0, 0);
    LOADCH(1, 1);

#pragma unroll 1
    for (int ch = 0; ch < KCHUNKS; ++ch) {
        const int s = ch % NSTAGE;
        asm volatile("cp.async.wait_group 1;" ::: "memory");
        __syncthreads();

        if (ch + 2 < KCHUNKS) {
            const int s2 = (ch + 2) % NSTAGE;
            LOADCH(ch + 2, s2);
        } else {
            asm volatile("cp.async.commit_group;" ::: "memory");
        }

        const uint32_t sa = sbase + s * STAGE_BYTES;
        const uint32_t sb = sa + A_STAGE_BYTES;
        // element (row, k-chunk c) stored at chunk c^(row&7); row&7 == g here.
        // a0/b0: k pair (16ks+2t) in chunk 2ks; a2/b1: k pair (16ks+8+2t) in chunk 2ks+1.
        const uint32_t abase = sa + (uint32_t)((wm * 32 + g) * 128 + t * 4);
        const uint32_t bbase = sb + (uint32_t)((wn * 64 + g) * 128 + t * 4);

#pragma unroll
        for (int ks = 0; ks < 4; ++ks) {
            const uint32_t x0 = (uint32_t)(((2 * ks)     ^ g) << 4);
            const uint32_t x1 = (uint32_t)(((2 * ks + 1) ^ g) << 4);

            unsigned af[2][4];
#pragma unroll
            for (int mt = 0; mt < 2; ++mt) {
                const uint32_t rb = abase + (uint32_t)(mt * 16 * 128);
                af[mt][0] = lds_u32(rb + x0);
                af[mt][1] = lds_u32(rb + 8 * 128 + x0);
                af[mt][2] = lds_u32(rb + x1);
                af[mt][3] = lds_u32(rb + 8 * 128 + x1);
            }
            unsigned bf[8][2];
#pragma unroll
            for (int nt = 0; nt < 8; ++nt) {
                const uint32_t rb = bbase + (uint32_t)(nt * 8 * 128);
                bf[nt][0] = lds_u32(rb + x0);
                bf[nt][1] = lds_u32(rb + x1);
            }
#pragma unroll
            for (int mt = 0; mt < 2; ++mt)
#pragma unroll
                for (int nt = 0; nt < 8; ++nt)
                    MMA_F16(c[mt][nt][0], c[mt][nt][1], c[mt][nt][2], c[mt][nt][3],
                            af[mt][0], af[mt][1], af[mt][2], af[mt][3],
                            bf[nt][0], bf[nt][1]);
        }
    }
#undef LOADCH

    // ---------------- epilogue ----------------
    float rs[2][2];
    rs[0][0] = rs[0][1] = rs[1][0] = rs[1][1] = 0.f;

#pragma unroll
    for (int mt = 0; mt < 2; ++mt) {
        const int row0 = brow + wm * 32 + mt * 16 + g;
#pragma unroll
        for (int nt = 0; nt < 8; ++nt) {
            const int col = bcol + wn * 64 + nt * 8 + 2 * t;
#pragma unroll
            for (int h = 0; h < 2; ++h) {
                const int row = row0 + h * 8;
                const size_t idx = (size_t)row * C_DIM + col;
                float v0 = c[mt][nt][h * 2 + 0];
                float v1 = c[mt][nt][h * 2 + 1];
                if (EPI == EPI_ELU) {
                    float2 bb = *(const float2*)&bias[col];
                    float a0 = v0 + bb.x, a1 = v1 + bb.y;
                    float h0 = (a0 > 0.f) ? a0 : expm1f(a0);
                    float h1 = (a1 > 0.f) ? a1 : expm1f(a1);
                    float e0 = (a0 > 0.f) ? 1.f : h0 + 1.f;
                    float e1 = (a1 > 0.f) ? 1.f : h1 + 1.f;
                    *(__half2*)((__half*)out0 + idx) = __floats2half2_rn(h0, h1);
                    *(float2*)&out1[idx] = make_float2(e0, e1);
                } else if (EPI == EPI_ADDY) {
                    float2 bb = *(const float2*)&bias[col];
                    float2 yv = *(const float2*)&aux[idx];
                    *(float2*)((float*)out0 + idx) =
                        make_float2(v0 + bb.x + yv.x, v1 + bb.y + yv.y);
                } else if (EPI == EPI_MULD) {
                    float2 dv = *(const float2*)&aux[idx];
                    *(__half2*)((__half*)out0 + idx) = __floats2half2_rn(v0 * dv.x, v1 * dv.y);
                } else {  // EPI_LAST
                    float2 vv = *(const float2*)&aux[idx];
                    rs[mt][h] += v0 * vv.x + v1 * vv.y;
                    *(__half2*)((__half*)out0 + idx) = __floats2half2_rn(v0, v1);
                }
            }
        }
    }

    if (EPI == EPI_LAST) {
#pragma unroll
        for (int mt = 0; mt < 2; ++mt)
#pragma unroll
            for (int h = 0; h < 2; ++h) {
                float s = rs[mt][h];
                s += __shfl_xor_sync(0xffffffffu, s, 1);
                s += __shfl_xor_sync(0xffffffffu, s, 2);
                if (t == 0)
                    atomicAdd(&acc[brow + wm * 32 + mt * 16 + g + h * 8], alpha * s);
            }
    }
}

// ---------------- aux kernels ----------------
__global__ void transpose_f2h(const float* __restrict__ in, __half* __restrict__ out)
{
    __shared__ float tile[32][33];
    int x = blockIdx.x * 32 + threadIdx.x;
    int y = blockIdx.y * 32 + threadIdx.y;
#pragma unroll
    for (int i = 0; i < 32; i += 8)
        tile[threadIdx.y + i][threadIdx.x] = in[(size_t)(y + i) * C_DIM + x];
    __syncthreads();
    x = blockIdx.y * 32 + threadIdx.x;
    y = blockIdx.x * 32 + threadIdx.y;
#pragma unroll
    for (int i = 0; i < 32; i += 8)
        out[(size_t)(y + i) * C_DIM + x] = __float2half_rn(tile[threadIdx.x][threadIdx.y + i]);
}

__global__ void f2h_copy(const float* __restrict__ in, __half* __restrict__ out)
{
    int i = (blockIdx.x * 256 + threadIdx.x) * 4;
    float4 v = *(const float4*)(in + i);
    __half2 lo = __floats2half2_rn(v.x, v.y);
    __half2 hi = __floats2half2_rn(v.z, v.w);
    *(uint2*)(out + i) = make_uint2(*(unsigned*)&lo, *(unsigned*)&hi);
}

__global__ void copy_f32(const float* __restrict__ in, float* __restrict__ out, int n)
{
    int i = blockIdx.x * blockDim.x + threadIdx.x;
    if (i < n) out[i] = in[i];
}

// ---------------- launch ----------------
extern "C" void kernel_launch(void* const* d_in, const int* in_sizes, int n_in,
                              void* d_out, int out_size)
{
    (void)in_sizes; (void)n_in; (void)out_size;

    const float* y   = (const float*)d_in[0];
    const float* ldj = (const float*)d_in[1];
    const float* v   = (const float*)d_in[2];
    const float* W1  = (const float*)d_in[3];
    const float* b1  = (const float*)d_in[4];
    const float* W2  = (const float*)d_in[5];
    const float* b2  = (const float*)d_in[6];
    const float* W3  = (const float*)d_in[7];
    const float* b3  = (const float*)d_in[8];

    float* zout  = (float*)d_out;
    float* ldout = zout + (size_t)B_ROWS * C_DIM;

    __half *h1, *h2, *t1, *t2, *wb, *yh, *vh;
    __half *w1h, *w2h, *w3h, *w1th, *w2th, *w3th;
    float *d1, *d2;
    cudaGetSymbolAddress((void**)&h1,   g_h1);
    cudaGetSymbolAddress((void**)&h2,   g_h2);
    cudaGetSymbolAddress((void**)&t1,   g_t1);
    cudaGetSymbolAddress((void**)&t2,   g_t2);
    cudaGetSymbolAddress((void**)&wb,   g_w);
    cudaGetSymbolAddress((void**)&yh,   g_yh);
    cudaGetSymbolAddress((void**)&vh,   g_vh);
    cudaGetSymbolAddress((void**)&d1,   g_d1);
    cudaGetSymbolAddress((void**)&d2,   g_d2);
    cudaGetSymbolAddress((void**)&w1h,  g_w1h);
    cudaGetSymbolAddress((void**)&w2h,  g_w2h);
    cudaGetSymbolAddress((void**)&w3h,  g_w3h);
    cudaGetSymbolAddress((void**)&w1th, g_w1th);
    cudaGetSymbolAddress((void**)&w2th, g_w2th);
    cudaGetSymbolAddress((void**)&w3th, g_w3th);

    cudaFuncSetAttribute(gemm_nt<EPI_ELU >, cudaFuncAttributeMaxDynamicSharedMemorySize, SMEM_TOTAL);
    cudaFuncSetAttribute(gemm_nt<EPI_ADDY>, cudaFuncAttributeMaxDynamicSharedMemorySize, SMEM_TOTAL);
    cudaFuncSetAttribute(gemm_nt<EPI_MULD>, cudaFuncAttributeMaxDynamicSharedMemorySize, SMEM_TOTAL);
    cudaFuncSetAttribute(gemm_nt<EPI_LAST>, cudaFuncAttributeMaxDynamicSharedMemorySize, SMEM_TOTAL);

    dim3 tgrid(C_DIM / 32, C_DIM / 32), tblk(32, 8);
    transpose_f2h<<<tgrid, tblk>>>(W1, w1th);
    transpose_f2h<<<tgrid, tblk>>>(W2, w2th);
    transpose_f2h<<<tgrid, tblk>>>(W3, w3th);

    const int wn = C_DIM * C_DIM / 1024;
    f2h_copy<<<wn, 256>>>(W1, w1h);
    f2h_copy<<<wn, 256>>>(W2, w2h);
    f2h_copy<<<wn, 256>>>(W3, w3h);
    const int bn = B_ROWS * C_DIM / 1024;
    f2h_copy<<<bn, 256>>>(y, yh);
    f2h_copy<<<bn, 256>>>(v, vh);

    copy_f32<<<B_ROWS / 256, 256>>>(ldj, ldout, B_ROWS);

    dim3 ggrid(C_DIM / TILE_N, B_ROWS / TILE_M);   // (8, 128)

    // forward
    gemm_nt<EPI_ELU ><<<ggrid, GEMM_THREADS, SMEM_TOTAL>>>(yh, w1h, b1, h1, d1, nullptr, 0.f, nullptr);
    gemm_nt<EPI_ELU ><<<ggrid, GEMM_THREADS, SMEM_TOTAL>>>(h1, w2h, b2, h2, d2, nullptr, 0.f, nullptr);
    gemm_nt<EPI_ADDY><<<ggrid, GEMM_THREADS, SMEM_TOTAL>>>(h2, w3h, b3, zout, nullptr, y, 0.f, nullptr);

    // power-series VJP iterations
    const __half* wcur = vh;
    for (int k = 1; k <= N_ITERS; ++k) {
        gemm_nt<EPI_MULD><<<ggrid, GEMM_THREADS, SMEM_TOTAL>>>(wcur, w3th, nullptr, t1, nullptr, d2, 0.f, nullptr);
        gemm_nt<EPI_MULD><<<ggrid, GEMM_THREADS, SMEM_TOTAL>>>(t1,   w2th, nullptr, t2, nullptr, d1, 0.f, nullptr);
        const float alpha = ((k & 1) ? 1.f : -1.f) / (float)k;
        gemm_nt<EPI_LAST><<<ggrid, GEMM_THREADS, SMEM_TOTAL>>>(t2,   w1th, nullptr, wb, nullptr, v, alpha, ldout);
        wcur = wb;
    }
}

// round 6
// speedup vs baseline: 2.8021x; 1.0171x over previous
#include <cuda_runtime.h>
#include <cuda_fp16.h>
#include <cstdint>

#define B_ROWS 16384
#define C_DIM  1024
#define N_ITERS 16

// ---- GEMM config: 128x128 tile, BK=64 halves (128B rows), 3-stage cp.async ----
#define TILE_M 128
#define TILE_N 128
#define BKC    64                       // 64 halves = 128B row
#define NSTAGE 3
#define A_STAGE_BYTES (TILE_M * 128)    // 16KB
#define B_STAGE_BYTES (TILE_N * 128)    // 16KB
#define STAGE_BYTES   (A_STAGE_BYTES + B_STAGE_BYTES)
#define SMEM_TOTAL    (NSTAGE * STAGE_BYTES + 1024)
#define KCHUNKS       (C_DIM / BKC)     // 16
#define GEMM_THREADS  256

// ---------------- static scratch ----------------
__device__ __half g_h1[(size_t)B_ROWS * C_DIM];
__device__ __half g_h2[(size_t)B_ROWS * C_DIM];
__device__ __half g_t1[(size_t)B_ROWS * C_DIM];
__device__ __half g_t2[(size_t)B_ROWS * C_DIM];
__device__ __half g_w [(size_t)B_ROWS * C_DIM];
__device__ __half g_yh[(size_t)B_ROWS * C_DIM];
__device__ __half g_vh[(size_t)B_ROWS * C_DIM];
__device__ __half g_d1[(size_t)B_ROWS * C_DIM];
__device__ __half g_d2[(size_t)B_ROWS * C_DIM];
__device__ __half g_w1h [(size_t)C_DIM * C_DIM];
__device__ __half g_w2h [(size_t)C_DIM * C_DIM];
__device__ __half g_w3h [(size_t)C_DIM * C_DIM];
__device__ __half g_w1th[(size_t)C_DIM * C_DIM];
__device__ __half g_w2th[(size_t)C_DIM * C_DIM];
__device__ __half g_w3th[(size_t)C_DIM * C_DIM];

// ---------------- helpers ----------------
__device__ __forceinline__ uint32_t smem_u32(const void* p) {
    uint32_t a;
    asm("{ .reg .u64 t; cvta.to.shared.u64 t, %1; cvt.u32.u64 %0, t; }" : "=r"(a) : "l"(p));
    return a;
}

#define LDSM4(R0, R1, R2, R3, addr)                                                 \
    asm volatile("ldmatrix.sync.aligned.m8n8.x4.shared.b16 {%0,%1,%2,%3}, [%4];"    \
                 : "=r"(R0), "=r"(R1), "=r"(R2), "=r"(R3) : "r"(addr))

#define MMA_F16(C0, C1, C2, C3, A0, A1, A2, A3, Bb0, Bb1)                           \
    asm volatile(                                                                   \
        "mma.sync.aligned.m16n8k16.row.col.f32.f16.f16.f32 "                        \
        "{%0,%1,%2,%3}, {%4,%5,%6,%7}, {%8,%9}, {%0,%1,%2,%3};"                     \
        : "+f"(C0), "+f"(C1), "+f"(C2), "+f"(C3)                                    \
        : "r"(A0), "r"(A1), "r"(A2), "r"(A3), "r"(Bb0), "r"(Bb1))

constexpr int EPI_ELU  = 0;  // out0(half) = elu(c+bias), out1(half) = elu'(c+bias)
constexpr int EPI_ADDY = 1;  // out0(f32)  = aux(f32) + c + bias
constexpr int EPI_MULD = 2;  // out0(half) = c * aux(half)
constexpr int EPI_LAST = 3;  // out0(half) = c; acc[row] += alpha * sum(c*aux(f32))

// NT GEMM: out[m,n] = sum_k A[m,k] * Bm[n,k];  A,Bm fp16, accum fp32
template <int EPI>
__global__ void __launch_bounds__(GEMM_THREADS, 2)
gemm_nt(const __half* __restrict__ A, const __half* __restrict__ Bm,
        const float* __restrict__ bias,
        void* __restrict__ out0, void* __restrict__ out1,
        const void* __restrict__ aux,
        float alpha, float* __restrict__ acc)
{
    extern __shared__ __align__(16) char dsm[];
    const uint32_t sbase = (smem_u32(dsm) + 1023u) & ~1023u;

    const int tid  = threadIdx.x;
    const int lane = tid & 31;
    const int warp = tid >> 5;
    const int wm   = warp & 3;   // 4 warps along M (32 rows)
    const int wn   = warp >> 2;  // 2 warps along N (64 cols)
    const int g    = lane >> 2;
    const int t    = lane & 3;

    // ldmatrix lane geometry: lanes 0-7 -> matrix0 rows, 8-15 -> m1, 16-23 -> m2, 24-31 -> m3
    const int Lrow  = (lane & 7) | (((lane >> 3) & 1) << 3);  // local row 0..15
    const int khalf = lane >> 4;                              // 0: k0-7, 1: k8-15
    const int r7    = Lrow & 7;                               // swizzle key (tile bases are x8)

    const int brow = blockIdx.y * TILE_M;
    const int bcol = blockIdx.x * TILE_N;
    const __half* Abase = A  + (size_t)brow * C_DIM;
    const __half* Bbase = Bm + (size_t)bcol * C_DIM;

    float c[2][8][4];
#pragma unroll
    for (int i = 0; i < 2; ++i)
#pragma unroll
        for (int j = 0; j < 8; ++j)
#pragma unroll
            for (int r = 0; r < 4; ++r) c[i][j][r] = 0.f;

// stage fill: 128 rows x 128B per operand; 256 threads x 4 x 16B per operand
#define LOADCH(ch, st)                                                            \
    do {                                                                          \
        const uint32_t sa_ = sbase + (st) * STAGE_BYTES;                          \
        const uint32_t sb_ = sa_ + A_STAGE_BYTES;                                 \
        const __half* ag_ = Abase + (ch) * BKC;                                   \
        const __half* bg_ = Bbase + (ch) * BKC;                                   \
        _Pragma("unroll")                                                         \
        for (int i_ = 0; i_ < 4; ++i_) {                                          \
            int l_ = i_ * GEMM_THREADS + tid; int r_ = l_ >> 3; int q_ = l_ & 7;  \
            uint32_t d_ = sa_ + (uint32_t)(r_ * 128) + (uint32_t)((q_ ^ (r_ & 7)) << 4); \
            const __half* s_ = ag_ + (size_t)r_ * C_DIM + q_ * 8;                 \
            asm volatile("cp.async.cg.shared.global [%0], [%1], 16;"              \
                         :: "r"(d_), "l"(s_) : "memory");                         \
        }                                                                         \
        _Pragma("unroll")                                                         \
        for (int i_ = 0; i_ < 4; ++i_) {                                          \
            int l_ = i_ * GEMM_THREADS + tid; int r_ = l_ >> 3; int q_ = l_ & 7;  \
            uint32_t d_ = sb_ + (uint32_t)(r_ * 128) + (uint32_t)((q_ ^ (r_ & 7)) << 4); \
            const __half* s_ = bg_ + (size_t)r_ * C_DIM + q_ * 8;                 \
            asm volatile("cp.async.cg.shared.global [%0], [%1], 16;"              \
                         :: "r"(d_), "l"(s_) : "memory");                         \
        }                                                                         \
        asm volatile("cp.async.commit_group;" ::: "memory");                      \
    } while (0)

    LOADCH(0, 0);
    LOADCH(1, 1);

#pragma unroll 1
    for (int ch = 0; ch < KCHUNKS; ++ch) {
        const int s = ch % NSTAGE;
        asm volatile("cp.async.wait_group 1;" ::: "memory");
        __syncthreads();

        if (ch + 2 < KCHUNKS) {
            const int s2 = (ch + 2) % NSTAGE;
            LOADCH(ch + 2, s2);
        } else {
            asm volatile("cp.async.commit_group;" ::: "memory");
        }

        const uint32_t sa = sbase + s * STAGE_BYTES;
        const uint32_t sb = sa + A_STAGE_BYTES;

        // per-lane row base addresses (swizzle XOR applied per-ks)
        uint32_t arow[2], brow4[4];
#pragma unroll
        for (int mt = 0; mt < 2; ++mt)
            arow[mt] = sa + (uint32_t)((wm * 32 + mt * 16 + Lrow) * 128);
#pragma unroll
        for (int n2 = 0; n2 < 4; ++n2)
            brow4[n2] = sb + (uint32_t)((wn * 64 + n2 * 16 + Lrow) * 128);

#pragma unroll
        for (int ks = 0; ks < 4; ++ks) {
            const uint32_t xoff = (uint32_t)(((2 * ks + khalf) ^ r7) << 4);

            unsigned af[2][4];
#pragma unroll
            for (int mt = 0; mt < 2; ++mt)
                LDSM4(af[mt][0], af[mt][1], af[mt][2], af[mt][3], arow[mt] + xoff);

            unsigned bf[8][2];
#pragma unroll
            for (int n2 = 0; n2 < 4; ++n2)
                LDSM4(bf[2 * n2][0], bf[2 * n2 + 1][0],
                      bf[2 * n2][1], bf[2 * n2 + 1][1], brow4[n2] + xoff);

#pragma unroll
            for (int mt = 0; mt < 2; ++mt)
#pragma unroll
                for (int nt = 0; nt < 8; ++nt)
                    MMA_F16(c[mt][nt][0], c[mt][nt][1], c[mt][nt][2], c[mt][nt][3],
                            af[mt][0], af[mt][1], af[mt][2], af[mt][3],
                            bf[nt][0], bf[nt][1]);
        }
    }
#undef LOADCH

    // ---------------- epilogue ----------------
    float rs[2][2];
    rs[0][0] = rs[0][1] = rs[1][0] = rs[1][1] = 0.f;

#pragma unroll
    for (int mt = 0; mt < 2; ++mt) {
        const int row0 = brow + wm * 32 + mt * 16 + g;
#pragma unroll
        for (int nt = 0; nt < 8; ++nt) {
            const int col = bcol + wn * 64 + nt * 8 + 2 * t;
#pragma unroll
            for (int h = 0; h < 2; ++h) {
                const int row = row0 + h * 8;
                const size_t idx = (size_t)row * C_DIM + col;
                float v0 = c[mt][nt][h * 2 + 0];
                float v1 = c[mt][nt][h * 2 + 1];
                if (EPI == EPI_ELU) {
                    float2 bb = *(const float2*)&bias[col];
                    float a0 = v0 + bb.x, a1 = v1 + bb.y;
                    float h0 = (a0 > 0.f) ? a0 : expm1f(a0);
                    float h1 = (a1 > 0.f) ? a1 : expm1f(a1);
                    float e0 = (a0 > 0.f) ? 1.f : h0 + 1.f;
                    float e1 = (a1 > 0.f) ? 1.f : h1 + 1.f;
                    *(__half2*)((__half*)out0 + idx) = __floats2half2_rn(h0, h1);
                    *(__half2*)((__half*)out1 + idx) = __floats2half2_rn(e0, e1);
                } else if (EPI == EPI_ADDY) {
                    float2 bb = *(const float2*)&bias[col];
                    float2 yv = *(const float2*)((const float*)aux + idx);
                    *(float2*)((float*)out0 + idx) =
                        make_float2(v0 + bb.x + yv.x, v1 + bb.y + yv.y);
                } else if (EPI == EPI_MULD) {
                    float2 dv = __half22float2(*(const __half2*)((const __half*)aux + idx));
                    *(__half2*)((__half*)out0 + idx) = __floats2half2_rn(v0 * dv.x, v1 * dv.y);
                } else {  // EPI_LAST
                    float2 vv = *(const float2*)((const float*)aux + idx);
                    rs[mt][h] += v0 * vv.x + v1 * vv.y;
                    *(__half2*)((__half*)out0 + idx) = __floats2half2_rn(v0, v1);
                }
            }
        }
    }

    if (EPI == EPI_LAST) {
#pragma unroll
        for (int mt = 0; mt < 2; ++mt)
#pragma unroll
            for (int h = 0; h < 2; ++h) {
                float s = rs[mt][h];
                s += __shfl_xor_sync(0xffffffffu, s, 1);
                s += __shfl_xor_sync(0xffffffffu, s, 2);
                if (t == 0)
                    atomicAdd(&acc[brow + wm * 32 + mt * 16 + g + h * 8], alpha * s);
            }
    }
}

// ---------------- aux kernels ----------------
__global__ void transpose_f2h(const float* __restrict__ in, __half* __restrict__ out)
{
    __shared__ float tile[32][33];
    int x = blockIdx.x * 32 + threadIdx.x;
    int y = blockIdx.y * 32 + threadIdx.y;
#pragma unroll
    for (int i = 0; i < 32; i += 8)
        tile[threadIdx.y + i][threadIdx.x] = in[(size_t)(y + i) * C_DIM + x];
    __syncthreads();
    x = blockIdx.y * 32 + threadIdx.x;
    y = blockIdx.x * 32 + threadIdx.y;
#pragma unroll
    for (int i = 0; i < 32; i += 8)
        out[(size_t)(y + i) * C_DIM + x] = __float2half_rn(tile[threadIdx.x][threadIdx.y + i]);
}

__global__ void f2h_copy(const float* __restrict__ in, __half* __restrict__ out)
{
    int i = (blockIdx.x * 256 + threadIdx.x) * 4;
    float4 v = *(const float4*)(in + i);
    __half2 lo = __floats2half2_rn(v.x, v.y);
    __half2 hi = __floats2half2_rn(v.z, v.w);
    *(uint2*)(out + i) = make_uint2(*(unsigned*)&lo, *(unsigned*)&hi);
}

__global__ void copy_f32(const float* __restrict__ in, float* __restrict__ out, int n)
{
    int i = blockIdx.x * blockDim.x + threadIdx.x;
    if (i < n) out[i] = in[i];
}

// ---------------- launch ----------------
extern "C" void kernel_launch(void* const* d_in, const int* in_sizes, int n_in,
                              void* d_out, int out_size)
{
    (void)in_sizes; (void)n_in; (void)out_size;

    const float* y   = (const float*)d_in[0];
    const float* ldj = (const float*)d_in[1];
    const float* v   = (const float*)d_in[2];
    const float* W1  = (const float*)d_in[3];
    const float* b1  = (const float*)d_in[4];
    const float* W2  = (const float*)d_in[5];
    const float* b2  = (const float*)d_in[6];
    const float* W3  = (const float*)d_in[7];
    const float* b3  = (const float*)d_in[8];

    float* zout  = (float*)d_out;
    float* ldout = zout + (size_t)B_ROWS * C_DIM;

    __half *h1, *h2, *t1, *t2, *wb, *yh, *vh, *d1, *d2;
    __half *w1h, *w2h, *w3h, *w1th, *w2th, *w3th;
    cudaGetSymbolAddress((void**)&h1,   g_h1);
    cudaGetSymbolAddress((void**)&h2,   g_h2);
    cudaGetSymbolAddress((void**)&t1,   g_t1);
    cudaGetSymbolAddress((void**)&t2,   g_t2);
    cudaGetSymbolAddress((void**)&wb,   g_w);
    cudaGetSymbolAddress((void**)&yh,   g_yh);
    cudaGetSymbolAddress((void**)&vh,   g_vh);
    cudaGetSymbolAddress((void**)&d1,   g_d1);
    cudaGetSymbolAddress((void**)&d2,   g_d2);
    cudaGetSymbolAddress((void**)&w1h,  g_w1h);
    cudaGetSymbolAddress((void**)&w2h,  g_w2h);
    cudaGetSymbolAddress((void**)&w3h,  g_w3h);
    cudaGetSymbolAddress((void**)&w1th, g_w1th);
    cudaGetSymbolAddress((void**)&w2th, g_w2th);
    cudaGetSymbolAddress((void**)&w3th, g_w3th);

    cudaFuncSetAttribute(gemm_nt<EPI_ELU >, cudaFuncAttributeMaxDynamicSharedMemorySize, SMEM_TOTAL);
    cudaFuncSetAttribute(gemm_nt<EPI_ADDY>, cudaFuncAttributeMaxDynamicSharedMemorySize, SMEM_TOTAL);
    cudaFuncSetAttribute(gemm_nt<EPI_MULD>, cudaFuncAttributeMaxDynamicSharedMemorySize, SMEM_TOTAL);
    cudaFuncSetAttribute(gemm_nt<EPI_LAST>, cudaFuncAttributeMaxDynamicSharedMemorySize, SMEM_TOTAL);

    dim3 tgrid(C_DIM / 32, C_DIM / 32), tblk(32, 8);
    transpose_f2h<<<tgrid, tblk>>>(W1, w1th);
    transpose_f2h<<<tgrid, tblk>>>(W2, w2th);
    transpose_f2h<<<tgrid, tblk>>>(W3, w3th);

    const int wn = C_DIM * C_DIM / 1024;
    f2h_copy<<<wn, 256>>>(W1, w1h);
    f2h_copy<<<wn, 256>>>(W2, w2h);
    f2h_copy<<<wn, 256>>>(W3, w3h);
    const int bn = B_ROWS * C_DIM / 1024;
    f2h_copy<<<bn, 256>>>(y, yh);
    f2h_copy<<<bn, 256>>>(v, vh);

    copy_f32<<<B_ROWS / 256, 256>>>(ldj, ldout, B_ROWS);

    dim3 ggrid(C_DIM / TILE_N, B_ROWS / TILE_M);   // (8, 128)

    // forward
    gemm_nt<EPI_ELU ><<<ggrid, GEMM_THREADS, SMEM_TOTAL>>>(yh, w1h, b1, h1, d1, nullptr, 0.f, nullptr);
    gemm_nt<EPI_ELU ><<<ggrid, GEMM_THREADS, SMEM_TOTAL>>>(h1, w2h, b2, h2, d2, nullptr, 0.f, nullptr);
    gemm_nt<EPI_ADDY><<<ggrid, GEMM_THREADS, SMEM_TOTAL>>>(h2, w3h, b3, zout, nullptr, y, 0.f, nullptr);

    // power-series VJP iterations
    const __half* wcur = vh;
    for (int k = 1; k <= N_ITERS; ++k) {
        gemm_nt<EPI_MULD><<<ggrid, GEMM_THREADS, SMEM_TOTAL>>>(wcur, w3th, nullptr, t1, nullptr, d2, 0.f, nullptr);
        gemm_nt<EPI_MULD><<<ggrid, GEMM_THREADS, SMEM_TOTAL>>>(t1,   w2th, nullptr, t2, nullptr, d1, 0.f, nullptr);
        const float alpha = ((k & 1) ? 1.f : -1.f) / (float)k;
        gemm_nt<EPI_LAST><<<ggrid, GEMM_THREADS, SMEM_TOTAL>>>(t2,   w1th, nullptr, wb, nullptr, v, alpha, ldout);
        wcur = wb;
    }
}

// round 7
// speedup vs baseline: 3.8523x; 1.3748x over previous
#include <cuda_runtime.h>
#include <cuda_fp16.h>
#include <cstdint>

#define B_ROWS 16384
#define C_DIM  1024
#define N_ITERS 16

// ---- GEMM config: 128x128 tile, BK=64 halves (128B rows), 3-stage cp.async ----
#define TILE_M 128
#define TILE_N 128
#define BKC    64
#define NSTAGE 3
#define A_STAGE_BYTES (TILE_M * 128)
#define B_STAGE_BYTES (TILE_N * 128)
#define STAGE_BYTES   (A_STAGE_BYTES + B_STAGE_BYTES)
#define SMEM_TOTAL    (NSTAGE * STAGE_BYTES + 1024)
#define KCHUNKS       (C_DIM / BKC)
#define GEMM_THREADS  256

// ---------------- static scratch ----------------
__device__ __half g_h1[(size_t)B_ROWS * C_DIM];
__device__ __half g_h2[(size_t)B_ROWS * C_DIM];
__device__ __half g_t1[(size_t)B_ROWS * C_DIM];
__device__ __half g_t2[(size_t)B_ROWS * C_DIM];
__device__ __half g_yh[(size_t)B_ROWS * C_DIM];
__device__ __half g_vh[(size_t)B_ROWS * C_DIM];
__device__ __half g_d1[(size_t)B_ROWS * C_DIM];
__device__ __half g_d2[(size_t)B_ROWS * C_DIM];
__device__ float  g_u [(size_t)B_ROWS * C_DIM];          // u = v @ W1^T (fp32)
__device__ __half g_w1h [(size_t)C_DIM * C_DIM];
__device__ __half g_w2h [(size_t)C_DIM * C_DIM];
__device__ __half g_w3h [(size_t)C_DIM * C_DIM];
__device__ __half g_w2th[(size_t)C_DIM * C_DIM];
__device__ __half g_w3th[(size_t)C_DIM * C_DIM];
__device__ __half g_m13 [(size_t)C_DIM * C_DIM];         // M[n,c] = (W1·W3)[c,n]

// ---------------- helpers ----------------
__device__ __forceinline__ uint32_t smem_u32(const void* p) {
    uint32_t a;
    asm("{ .reg .u64 t; cvta.to.shared.u64 t, %1; cvt.u32.u64 %0, t; }" : "=r"(a) : "l"(p));
    return a;
}

#define LDSM4(R0, R1, R2, R3, addr)                                                 \
    asm volatile("ldmatrix.sync.aligned.m8n8.x4.shared.b16 {%0,%1,%2,%3}, [%4];"    \
                 : "=r"(R0), "=r"(R1), "=r"(R2), "=r"(R3) : "r"(addr))

#define MMA_F16(C0, C1, C2, C3, A0, A1, A2, A3, Bb0, Bb1)                           \
    asm volatile(                                                                   \
        "mma.sync.aligned.m16n8k16.row.col.f32.f16.f16.f32 "                        \
        "{%0,%1,%2,%3}, {%4,%5,%6,%7}, {%8,%9}, {%0,%1,%2,%3};"                     \
        : "+f"(C0), "+f"(C1), "+f"(C2), "+f"(C3)                                    \
        : "r"(A0), "r"(A1), "r"(A2), "r"(A3), "r"(Bb0), "r"(Bb1))

constexpr int EPI_ELU      = 0;  // out0(h) = elu(c+bias), out1(h) = elu'
constexpr int EPI_ADDY     = 1;  // out0(f) = aux(f) + c + bias
constexpr int EPI_MULD     = 2;  // out0(h) = c * aux(h)
constexpr int EPI_MULD_DOT = 3;  // val = c*aux(h); out0(h)=val; acc += alpha*sum(val*aux2(f))
constexpr int EPI_STOREH   = 4;  // out0(h) = c
constexpr int EPI_STOREF   = 5;  // out0(f) = c

// NT GEMM: out[m,n] = sum_k A[m,k] * Bm[n,k]
template <int EPI>
__global__ void __launch_bounds__(GEMM_THREADS, 2)
gemm_nt(const __half* __restrict__ A, const __half* __restrict__ Bm,
        const float* __restrict__ bias,
        void* __restrict__ out0, void* __restrict__ out1,
        const void* __restrict__ aux, const float* __restrict__ aux2,
        float alpha, float* __restrict__ acc)
{
    extern __shared__ __align__(16) char dsm[];
    const uint32_t sbase = (smem_u32(dsm) + 1023u) & ~1023u;

    const int tid  = threadIdx.x;
    const int lane = tid & 31;
    const int warp = tid >> 5;
    const int wm   = warp & 3;
    const int wn   = warp >> 2;
    const int g    = lane >> 2;
    const int t    = lane & 3;

    const int Lrow  = (lane & 7) | (((lane >> 3) & 1) << 3);
    const int khalf = lane >> 4;
    const int r7    = Lrow & 7;

    const int brow = blockIdx.y * TILE_M;
    const int bcol = blockIdx.x * TILE_N;
    const __half* Abase = A  + (size_t)brow * C_DIM;
    const __half* Bbase = Bm + (size_t)bcol * C_DIM;

    float c[2][8][4];
#pragma unroll
    for (int i = 0; i < 2; ++i)
#pragma unroll
        for (int j = 0; j < 8; ++j)
#pragma unroll
            for (int r = 0; r < 4; ++r) c[i][j][r] = 0.f;

#define LOADCH(ch, st)                                                            \
    do {                                                                          \
        const uint32_t sa_ = sbase + (st) * STAGE_BYTES;                          \
        const uint32_t sb_ = sa_ + A_STAGE_BYTES;                                 \
        const __half* ag_ = Abase + (ch) * BKC;                                   \
        const __half* bg_ = Bbase + (ch) * BKC;                                   \
        _Pragma("unroll")                                                         \
        for (int i_ = 0; i_ < 4; ++i_) {                                          \
            int l_ = i_ * GEMM_THREADS + tid; int r_ = l_ >> 3; int q_ = l_ & 7;  \
            uint32_t d_ = sa_ + (uint32_t)(r_ * 128) + (uint32_t)((q_ ^ (r_ & 7)) << 4); \
            const __half* s_ = ag_ + (size_t)r_ * C_DIM + q_ * 8;                 \
            asm volatile("cp.async.cg.shared.global [%0], [%1], 16;"              \
                         :: "r"(d_), "l"(s_) : "memory");                         \
        }                                                                         \
        _Pragma("unroll")                                                         \
        for (int i_ = 0; i_ < 4; ++i_) {                                          \
            int l_ = i_ * GEMM_THREADS + tid; int r_ = l_ >> 3; int q_ = l_ & 7;  \
            uint32_t d_ = sb_ + (uint32_t)(r_ * 128) + (uint32_t)((q_ ^ (r_ & 7)) << 4); \
            const __half* s_ = bg_ + (size_t)r_ * C_DIM + q_ * 8;                 \
            asm volatile("cp.async.cg.shared.global [%0], [%1], 16;"              \
                         :: "r"(d_), "l"(s_) : "memory");                         \
        }                                                                         \
        asm volatile("cp.async.commit_group;" ::: "memory");                      \
    } while (0)

    LOADCH(0, 0);
    LOADCH(1, 1);

#pragma unroll 1
    for (int ch = 0; ch < KCHUNKS; ++ch) {
        const int s = ch % NSTAGE;
        asm volatile("cp.async.wait_group 1;" ::: "memory");
        __syncthreads();

        if (ch + 2 < KCHUNKS) {
            const int s2 = (ch + 2) % NSTAGE;
            LOADCH(ch + 2, s2);
        } else {
            asm volatile("cp.async.commit_group;" ::: "memory");
        }

        const uint32_t sa = sbase + s * STAGE_BYTES;
        const uint32_t sb = sa + A_STAGE_BYTES;

        uint32_t arow[2], brow4[4];
#pragma unroll
        for (int mt = 0; mt < 2; ++mt)
            arow[mt] = sa + (uint32_t)((wm * 32 + mt * 16 + Lrow) * 128);
#pragma unroll
        for (int n2 = 0; n2 < 4; ++n2)
            brow4[n2] = sb + (uint32_t)((wn * 64 + n2 * 16 + Lrow) * 128);

#pragma unroll
        for (int ks = 0; ks < 4; ++ks) {
            const uint32_t xoff = (uint32_t)(((2 * ks + khalf) ^ r7) << 4);

            unsigned af[2][4];
#pragma unroll
            for (int mt = 0; mt < 2; ++mt)
                LDSM4(af[mt][0], af[mt][1], af[mt][2], af[mt][3], arow[mt] + xoff);

            unsigned bf[8][2];
#pragma unroll
            for (int n2 = 0; n2 < 4; ++n2)
                LDSM4(bf[2 * n2][0], bf[2 * n2 + 1][0],
                      bf[2 * n2][1], bf[2 * n2 + 1][1], brow4[n2] + xoff);

#pragma unroll
            for (int mt = 0; mt < 2; ++mt)
#pragma unroll
                for (int nt = 0; nt < 8; ++nt)
                    MMA_F16(c[mt][nt][0], c[mt][nt][1], c[mt][nt][2], c[mt][nt][3],
                            af[mt][0], af[mt][1], af[mt][2], af[mt][3],
                            bf[nt][0], bf[nt][1]);
        }
    }
#undef LOADCH

    // ---------------- epilogue ----------------
    float rs[2][2];
    rs[0][0] = rs[0][1] = rs[1][0] = rs[1][1] = 0.f;

#pragma unroll
    for (int mt = 0; mt < 2; ++mt) {
        const int row0 = brow + wm * 32 + mt * 16 + g;
#pragma unroll
        for (int nt = 0; nt < 8; ++nt) {
            const int col = bcol + wn * 64 + nt * 8 + 2 * t;
#pragma unroll
            for (int h = 0; h < 2; ++h) {
                const int row = row0 + h * 8;
                const size_t idx = (size_t)row * C_DIM + col;
                float v0 = c[mt][nt][h * 2 + 0];
                float v1 = c[mt][nt][h * 2 + 1];
                if (EPI == EPI_ELU) {
                    float2 bb = *(const float2*)&bias[col];
                    float a0 = v0 + bb.x, a1 = v1 + bb.y;
                    float h0 = (a0 > 0.f) ? a0 : expm1f(a0);
                    float h1 = (a1 > 0.f) ? a1 : expm1f(a1);
                    float e0 = (a0 > 0.f) ? 1.f : h0 + 1.f;
                    float e1 = (a1 > 0.f) ? 1.f : h1 + 1.f;
                    *(__half2*)((__half*)out0 + idx) = __floats2half2_rn(h0, h1);
                    *(__half2*)((__half*)out1 + idx) = __floats2half2_rn(e0, e1);
                } else if (EPI == EPI_ADDY) {
                    float2 bb = *(const float2*)&bias[col];
                    float2 yv = *(const float2*)((const float*)aux + idx);
                    *(float2*)((float*)out0 + idx) =
                        make_float2(v0 + bb.x + yv.x, v1 + bb.y + yv.y);
                } else if (EPI == EPI_MULD) {
                    float2 dv = __half22float2(*(const __half2*)((const __half*)aux + idx));
                    *(__half2*)((__half*)out0 + idx) = __floats2half2_rn(v0 * dv.x, v1 * dv.y);
                } else if (EPI == EPI_MULD_DOT) {
                    float2 dv = __half22float2(*(const __half2*)((const __half*)aux + idx));
                    float n0 = v0 * dv.x, n1 = v1 * dv.y;
                    *(__half2*)((__half*)out0 + idx) = __floats2half2_rn(n0, n1);
                    float2 uu = *(const float2*)(aux2 + idx);
                    rs[mt][h] += n0 * uu.x + n1 * uu.y;
                } else if (EPI == EPI_STOREH) {
                    *(__half2*)((__half*)out0 + idx) = __floats2half2_rn(v0, v1);
                } else {  // EPI_STOREF
                    *(float2*)((float*)out0 + idx) = make_float2(v0, v1);
                }
            }
        }
    }

    if (EPI == EPI_MULD_DOT) {
#pragma unroll
        for (int mt = 0; mt < 2; ++mt)
#pragma unroll
            for (int h = 0; h < 2; ++h) {
                float s = rs[mt][h];
                s += __shfl_xor_sync(0xffffffffu, s, 1);
                s += __shfl_xor_sync(0xffffffffu, s, 2);
                if (t == 0)
                    atomicAdd(&acc[brow + wm * 32 + mt * 16 + g + h * 8], alpha * s);
            }
    }
}

// ---------------- aux kernels ----------------
__global__ void transpose_f2h(const float* __restrict__ in, __half* __restrict__ out)
{
    __shared__ float tile[32][33];
    int x = blockIdx.x * 32 + threadIdx.x;
    int y = blockIdx.y * 32 + threadIdx.y;
#pragma unroll
    for (int i = 0; i < 32; i += 8)
        tile[threadIdx.y + i][threadIdx.x] = in[(size_t)(y + i) * C_DIM + x];
    __syncthreads();
    x = blockIdx.y * 32 + threadIdx.x;
    y = blockIdx.x * 32 + threadIdx.y;
#pragma unroll
    for (int i = 0; i < 32; i += 8)
        out[(size_t)(y + i) * C_DIM + x] = __float2half_rn(tile[threadIdx.x][threadIdx.y + i]);
}

__global__ void f2h_copy(const float* __restrict__ in, __half* __restrict__ out)
{
    int i = (blockIdx.x * 256 + threadIdx.x) * 4;
    float4 v = *(const float4*)(in + i);
    __half2 lo = __floats2half2_rn(v.x, v.y);
    __half2 hi = __floats2half2_rn(v.z, v.w);
    *(uint2*)(out + i) = make_uint2(*(unsigned*)&lo, *(unsigned*)&hi);
}

__global__ void copy_f32(const float* __restrict__ in, float* __restrict__ out, int n)
{
    int i = blockIdx.x * blockDim.x + threadIdx.x;
    if (i < n) out[i] = in[i];
}

// ---------------- launch ----------------
extern "C" void kernel_launch(void* const* d_in, const int* in_sizes, int n_in,
                              void* d_out, int out_size)
{
    (void)in_sizes; (void)n_in; (void)out_size;

    const float* y   = (const float*)d_in[0];
    const float* ldj = (const float*)d_in[1];
    const float* v   = (const float*)d_in[2];
    const float* W1  = (const float*)d_in[3];
    const float* b1  = (const float*)d_in[4];
    const float* W2  = (const float*)d_in[5];
    const float* b2  = (const float*)d_in[6];
    const float* W3  = (const float*)d_in[7];
    const float* b3  = (const float*)d_in[8];

    float* zout  = (float*)d_out;
    float* ldout = zout + (size_t)B_ROWS * C_DIM;

    __half *h1, *h2, *t1, *t2, *yh, *vh, *d1, *d2, *m13;
    __half *w1h, *w2h, *w3h, *w2th, *w3th;
    float *u;
    cudaGetSymbolAddress((void**)&h1,   g_h1);
    cudaGetSymbolAddress((void**)&h2,   g_h2);
    cudaGetSymbolAddress((void**)&t1,   g_t1);
    cudaGetSymbolAddress((void**)&t2,   g_t2);
    cudaGetSymbolAddress((void**)&yh,   g_yh);
    cudaGetSymbolAddress((void**)&vh,   g_vh);
    cudaGetSymbolAddress((void**)&d1,   g_d1);
    cudaGetSymbolAddress((void**)&d2,   g_d2);
    cudaGetSymbolAddress((void**)&u,    g_u);
    cudaGetSymbolAddress((void**)&m13,  g_m13);
    cudaGetSymbolAddress((void**)&w1h,  g_w1h);
    cudaGetSymbolAddress((void**)&w2h,  g_w2h);
    cudaGetSymbolAddress((void**)&w3h,  g_w3h);
    cudaGetSymbolAddress((void**)&w2th, g_w2th);
    cudaGetSymbolAddress((void**)&w3th, g_w3th);

    cudaFuncSetAttribute(gemm_nt<EPI_ELU     >, cudaFuncAttributeMaxDynamicSharedMemorySize, SMEM_TOTAL);
    cudaFuncSetAttribute(gemm_nt<EPI_ADDY    >, cudaFuncAttributeMaxDynamicSharedMemorySize, SMEM_TOTAL);
    cudaFuncSetAttribute(gemm_nt<EPI_MULD    >, cudaFuncAttributeMaxDynamicSharedMemorySize, SMEM_TOTAL);
    cudaFuncSetAttribute(gemm_nt<EPI_MULD_DOT>, cudaFuncAttributeMaxDynamicSharedMemorySize, SMEM_TOTAL);
    cudaFuncSetAttribute(gemm_nt<EPI_STOREH  >, cudaFuncAttributeMaxDynamicSharedMemorySize, SMEM_TOTAL);
    cudaFuncSetAttribute(gemm_nt<EPI_STOREF  >, cudaFuncAttributeMaxDynamicSharedMemorySize, SMEM_TOTAL);

    dim3 tgrid(C_DIM / 32, C_DIM / 32), tblk(32, 8);
    transpose_f2h<<<tgrid, tblk>>>(W2, w2th);
    transpose_f2h<<<tgrid, tblk>>>(W3, w3th);

    const int wn = C_DIM * C_DIM / 1024;
    f2h_copy<<<wn, 256>>>(W1, w1h);
    f2h_copy<<<wn, 256>>>(W2, w2h);
    f2h_copy<<<wn, 256>>>(W3, w3h);
    const int bn = B_ROWS * C_DIM / 1024;
    f2h_copy<<<bn, 256>>>(y, yh);
    f2h_copy<<<bn, 256>>>(v, vh);

    copy_f32<<<B_ROWS / 256, 256>>>(ldj, ldout, B_ROWS);

    dim3 ggrid(C_DIM / TILE_N, B_ROWS / TILE_M);   // (8, 128)
    dim3 sgrid(C_DIM / TILE_N, C_DIM / TILE_M);    // (8, 8)  small 1024^3 GEMM

    // forward: h1,d1 ; h2,d2 ; z = y + g(y)
    gemm_nt<EPI_ELU ><<<ggrid, GEMM_THREADS, SMEM_TOTAL>>>(yh, w1h, b1, h1, d1, nullptr, nullptr, 0.f, nullptr);
    gemm_nt<EPI_ELU ><<<ggrid, GEMM_THREADS, SMEM_TOTAL>>>(h1, w2h, b2, h2, d2, nullptr, nullptr, 0.f, nullptr);
    gemm_nt<EPI_ADDY><<<ggrid, GEMM_THREADS, SMEM_TOTAL>>>(h2, w3h, b3, zout, nullptr, y, nullptr, 0.f, nullptr);

    // u = v @ W1^T  (fp32 store; used by every iteration's dot)
    gemm_nt<EPI_STOREF><<<ggrid, GEMM_THREADS, SMEM_TOTAL>>>(vh, w1h, nullptr, u, nullptr, nullptr, nullptr, 0.f, nullptr);

    // M[n,c] = (W1·W3)[c,n]:  out[m,n] = sum_k W3^T[m,k]·W1[n,k] = (W1·W3)[n,m]
    gemm_nt<EPI_STOREH><<<sgrid, GEMM_THREADS, SMEM_TOTAL>>>(w3th, w1h, nullptr, m13, nullptr, nullptr, nullptr, 0.f, nullptr);

    // power-series: per k, two GEMMs.
    //   k=1:  t1 = (v·W3)∘d2          (B = W3^T)
    //   k>1:  t1 = (t2·(W1·W3))∘d2    (B = m13)
    //   all:  t2 = (t1·W2)∘d1; acc += alpha_k * rowdot(t2, u)
    for (int k = 1; k <= N_ITERS; ++k) {
        if (k == 1)
            gemm_nt<EPI_MULD><<<ggrid, GEMM_THREADS, SMEM_TOTAL>>>(vh, w3th, nullptr, t1, nullptr, d2, nullptr, 0.f, nullptr);
        else
            gemm_nt<EPI_MULD><<<ggrid, GEMM_THREADS, SMEM_TOTAL>>>(t2, m13, nullptr, t1, nullptr, d2, nullptr, 0.f, nullptr);
        const float alpha = ((k & 1) ? 1.f : -1.f) / (float)k;
        gemm_nt<EPI_MULD_DOT><<<ggrid, GEMM_THREADS, SMEM_TOTAL>>>(t1, w2th, nullptr, t2, nullptr, d1, u, alpha, ldout);
    }
}